// round 2
// baseline (speedup 1.0000x reference)
// multigrancnn GB300 — R2: resubmit R1 fp32 implementation (infra flake last round),
// with launch_bounds hardening. Fused M-pool GEMM; sigmoid/max commuted.
#include <cuda_runtime.h>
#include <math.h>
#include <float.h>

#define BT 256

// ---------------- static scratch ----------------
__device__ float g_qpad [16*247*1024];
__device__ float g_qc1  [16*246*300];
__device__ float g_qp1p [16*168*300];
__device__ float g_qc2  [16*167*300];
__device__ float g_qp2p [16*88*300];
__device__ float g_qc3  [16*87*300];
__device__ float g_qg   [16*480*300];
__device__ float g_dpad [80u*487*1024];
__device__ float g_dc1  [80u*486*300];
__device__ float g_dp1p [80u*328*300];
__device__ float g_dc2  [80u*327*300];
__device__ float g_dp2p [80u*168*300];
__device__ float g_dc3  [80u*167*300];
__device__ float g_dg   [80u*960*300];
__device__ float g_qt   [16*480*300];
__device__ float g_x0   [80*40*40];
__device__ float g_x1   [80*40*40];

// ---------------- helpers ----------------
__device__ __forceinline__ unsigned f2u(float f){
    unsigned u = __float_as_uint(f);
    return (u & 0x80000000u) ? ~u : (u | 0x80000000u);
}
__device__ __forceinline__ float u2f(unsigned u){
    unsigned b = (u & 0x80000000u) ? (u ^ 0x80000000u) : ~u;
    return __uint_as_float(b);
}
__device__ __forceinline__ float sigm(float x){ return 1.f/(1.f + expf(-x)); }

// block-wide sum reduce of v (256 threads). cell: one shared int.
__device__ __forceinline__ int block_reduce_sum(int v, int tid, int* cell){
    #pragma unroll
    for (int off=16; off; off>>=1) v += __shfl_down_sync(0xffffffffu, v, off);
    if (tid==0) *cell = 0;
    __syncthreads();
    if ((tid & 31)==0) atomicAdd(cell, v);
    __syncthreads();
    int t = *cell;
    __syncthreads();
    return t;
}
// exclusive scan across 256 threads; sh size 256. total returned via *total.
__device__ __forceinline__ int block_scan_excl(int v, int tid, int* sh, int* total){
    sh[tid] = v; __syncthreads();
    #pragma unroll
    for (int off=1; off<256; off<<=1){
        int t = (tid>=off) ? sh[tid-off] : 0;
        __syncthreads();
        sh[tid] += t;
        __syncthreads();
    }
    *total = sh[255];
    int res = sh[tid] - v;
    __syncthreads();
    return res;
}

// top-k of skey[0..n), keep original order, ties broken by lowest index.
// writes k indices (ascending) into out_idx. sws: int[257] shared workspace.
__device__ void topk_select(const unsigned* skey, int n, int k, short* out_idx,
                            int* sws, int tid){
    unsigned lo = 0u, hi = 0xFFFFFFFFu;
    while (lo < hi){
        unsigned mid = lo + ((hi - lo) >> 1) + 1u;
        int c = 0;
        for (int i=tid; i<n; i+=BT) c += (skey[i] >= mid);
        int tot = block_reduce_sum(c, tid, sws+256);
        if (tot >= k) lo = mid; else hi = mid - 1u;
    }
    unsigned T = lo;
    int c = 0;
    for (int i=tid; i<n; i+=BT) c += (skey[i] > T);
    int cnt_gt = block_reduce_sum(c, tid, sws+256);
    int m_eq = k - cnt_gt;

    int ipt = (n + BT - 1)/BT;
    int beg = tid*ipt; if (beg > n) beg = n;
    int end = beg + ipt; if (end > n) end = n;

    int ceq = 0;
    for (int i=beg; i<end; i++) ceq += (skey[i]==T);
    int tot_d;
    int eq_base = block_scan_excl(ceq, tid, sws, &tot_d);

    int csel = 0;
    { int eqr = eq_base;
      for (int i=beg; i<end; i++){
          unsigned v = skey[i]; int e = (v==T);
          int s = (v>T) || (e && eqr < m_eq);
          eqr += e; csel += s;
      } }
    int out_base = block_scan_excl(csel, tid, sws, &tot_d);
    { int eqr = eq_base; int p = out_base;
      for (int i=beg; i<end; i++){
          unsigned v = skey[i]; int e = (v==T);
          int s = (v>T) || (e && eqr < m_eq);
          eqr += e;
          if (s) out_idx[p++] = (short)i;
      } }
    __syncthreads();
}

// ---------------- pad kernels ----------------
__global__ void __launch_bounds__(256) pad_rows_kernel(
        float* dst, const float* __restrict__ src,
        int L, int C, int srcRowsPerItem, int srcRowOffset){
    int n = blockIdx.y;
    int idx = blockIdx.x*blockDim.x + threadIdx.x;
    int LP = L + 8;
    if (idx >= LP*C) return;
    int l = idx / C, c = idx - l*C;
    float v = 0.f;
    if (l >= 4 && l < 4+L)
        v = src[((size_t)n*srcRowsPerItem + srcRowOffset + (l-4))*C + c];
    dst[(size_t)n*LP*C + idx] = v;
}

__global__ void __launch_bounds__(256) pad_docs_kernel(
        float* dst, const float* __restrict__ pos, const float* __restrict__ neg){
    const int LP = 487, C = 1024, L = 479;
    int n = blockIdx.y;
    int idx = blockIdx.x*blockDim.x + threadIdx.x;
    if (idx >= LP*C) return;
    int l = idx / C, c = idx - l*C;
    float v = 0.f;
    if (l >= 4 && l < 4+L){
        int s = n >> 4, b = n & 15;
        const float* src = (s==0) ? (pos + (size_t)b*L*C)
                                  : (neg + ((size_t)(s-1)*16 + b)*L*C);
        v = src[(size_t)(l-4)*C + c];
    }
    dst[(size_t)n*LP*C + idx] = v;
}

// ---------------- kmax over channel axis (1024 -> 300) ----------------
__global__ void __launch_bounds__(256) kmax_last1024_kernel(
        const float* __restrict__ src, int Lpad,
        float* __restrict__ dst, int dstNstride){
    __shared__ unsigned skey[1024];
    __shared__ short    sidx[300];
    __shared__ int      sws[257];
    int tid = threadIdx.x;
    int l = blockIdx.x, n = blockIdx.y;
    const float* row = src + ((size_t)n*Lpad + 4 + l)*1024;
    for (int i=tid; i<1024; i+=BT) skey[i] = f2u(row[i]);
    __syncthreads();
    topk_select(skey, 1024, 300, sidx, sws, tid);
    float* orow = dst + (size_t)n*dstNstride + (size_t)l*300;
    for (int j=tid; j<300; j+=BT) orow[j] = u2f(skey[sidx[j]]);
}

// ---------------- kmax over length axis ----------------
__global__ void __launch_bounds__(256) kmax_len_kernel(
        const float* __restrict__ src, int Lin, int k,
        float* __restrict__ dstBase, int dstNstride){
    __shared__ unsigned skey[512];
    __shared__ short    sidx[320];
    __shared__ int      sws[257];
    int tid = threadIdx.x;
    int o = blockIdx.x, n = blockIdx.y;
    for (int l=tid; l<Lin; l+=BT)
        skey[l] = f2u(src[((size_t)n*Lin + l)*300 + o]);
    __syncthreads();
    topk_select(skey, Lin, k, sidx, sws, tid);
    float* dn = dstBase + (size_t)n*dstNstride;
    for (int j=tid; j<k; j+=BT)
        dn[(size_t)j*300 + o] = u2f(skey[sidx[j]]);
}

// ---------------- conv1d(k=2)+tanh as GEMM ----------------
// in (N, Lpad, Cin), w (300, Cin, 2), out (N, Lout=Lpad-1, 300)
__global__ void __launch_bounds__(256) conv1d_tanh_kernel(
        const float* __restrict__ in, const float* __restrict__ w,
        const float* __restrict__ bias, float* __restrict__ out,
        int Lpad, int Lout, int Cin){
    __shared__ float sA[16][68];       // [kk][l], 65 l's used
    __shared__ float sW[2][16][68];    // [tap][kk][o]
    int tid = threadIdx.x;
    int tx = tid & 15, ty = tid >> 4;
    int l0 = blockIdx.x * 64;
    int o0 = blockIdx.y * 64;
    int n  = blockIdx.z;
    const float* inN = in + (size_t)n * Lpad * Cin;
    float acc[4][4];
    #pragma unroll
    for (int i=0;i<4;i++)
        #pragma unroll
        for (int j=0;j<4;j++) acc[i][j] = 0.f;
    int row = ty*4, col = tx*4;
    for (int c0 = 0; c0 < Cin; c0 += 16){
        for (int idx = tid; idx < 65*16; idx += BT){
            int kk = idx & 15, l = idx >> 4;
            int gl = l0 + l, gc = c0 + kk;
            float v = 0.f;
            if (gl < Lpad && gc < Cin) v = inN[(size_t)gl*Cin + gc];
            sA[kk][l] = v;
        }
        for (int idx = tid; idx < 2048; idx += BT){
            int t = idx & 1, kk = (idx >> 1) & 15, o = idx >> 5;
            int go = o0 + o, gc = c0 + kk;
            float v = 0.f;
            if (go < 300 && gc < Cin) v = w[((size_t)go*Cin + gc)*2 + t];
            sW[t][kk][o] = v;
        }
        __syncthreads();
        #pragma unroll
        for (int kk=0; kk<16; kk++){
            float4 a4 = *(const float4*)&sA[kk][row];
            float  a5 = sA[kk][row+4];
            float4 b0 = *(const float4*)&sW[0][kk][col];
            float4 b1 = *(const float4*)&sW[1][kk][col];
            float A0[4] = {a4.x, a4.y, a4.z, a4.w};
            float A1[4] = {a4.y, a4.z, a4.w, a5};
            float B0[4] = {b0.x, b0.y, b0.z, b0.w};
            float B1[4] = {b1.x, b1.y, b1.z, b1.w};
            #pragma unroll
            for (int i=0;i<4;i++)
                #pragma unroll
                for (int j=0;j<4;j++)
                    acc[i][j] += A0[i]*B0[j] + A1[i]*B1[j];
        }
        __syncthreads();
    }
    #pragma unroll
    for (int i=0;i<4;i++){
        int gl = l0 + row + i;
        if (gl >= Lout) continue;
        #pragma unroll
        for (int j=0;j<4;j++){
            int go = o0 + col + j;
            if (go < 300)
                out[((size_t)n*Lout + gl)*300 + go] = tanhf(acc[i][j] + bias[go]);
        }
    }
}

// ---------------- generic SGEMM: C(M,N) = A(M,K) * B(K,N) ----------------
__global__ void __launch_bounds__(256) sgemm_kernel(
        const float* __restrict__ A, const float* __restrict__ B,
        float* __restrict__ C, int M, int N, int K){
    __shared__ float sA[16][68];
    __shared__ float sB[16][68];
    int tid = threadIdx.x;
    int tx = tid & 15, ty = tid >> 4;
    int n0 = blockIdx.x * 64, m0 = blockIdx.y * 64;
    float acc[4][4];
    #pragma unroll
    for (int i=0;i<4;i++)
        #pragma unroll
        for (int j=0;j<4;j++) acc[i][j] = 0.f;
    int row = ty*4, col = tx*4;
    for (int k0 = 0; k0 < K; k0 += 16){
        for (int idx = tid; idx < 1024; idx += BT){
            int kk = idx & 15, m = idx >> 4;
            int gm = m0 + m, gk = k0 + kk;
            sA[kk][m] = (gm < M && gk < K) ? A[(size_t)gm*K + gk] : 0.f;
        }
        for (int idx = tid; idx < 1024; idx += BT){
            int nn = idx & 63, kk = idx >> 6;
            int gn = n0 + nn, gk = k0 + kk;
            sB[kk][nn] = (gn < N && gk < K) ? B[(size_t)gk*N + gn] : 0.f;
        }
        __syncthreads();
        #pragma unroll
        for (int kk=0; kk<16; kk++){
            float4 a4 = *(const float4*)&sA[kk][row];
            float4 b4 = *(const float4*)&sB[kk][col];
            float Aa[4] = {a4.x,a4.y,a4.z,a4.w};
            float Bb[4] = {b4.x,b4.y,b4.z,b4.w};
            #pragma unroll
            for (int i=0;i<4;i++)
                #pragma unroll
                for (int j=0;j<4;j++) acc[i][j] += Aa[i]*Bb[j];
        }
        __syncthreads();
    }
    #pragma unroll
    for (int i=0;i<4;i++){
        int gm = m0 + row + i;
        if (gm >= M) continue;
        #pragma unroll
        for (int j=0;j<4;j++){
            int gn = n0 + col + j;
            if (gn < N) C[(size_t)gm*N + gn] = acc[i][j];
        }
    }
}

// ---------------- fused match GEMM + 12x24 max-pool + sigmoid ----------------
// tile: 48 q rows x 96 d rows = 4x4 pooled cells. 288 threads, 4x4 per thread.
__global__ void __launch_bounds__(288) mpool_kernel(
        const float* __restrict__ qt, const float* __restrict__ dg,
        const float* __restrict__ bbp, float* __restrict__ xout){
    __shared__ float sQ[20][52];
    __shared__ float sD[20][100];
    __shared__ unsigned pool[16];
    int tid = threadIdx.x;
    int n = blockIdx.z, b = n & 15;
    int q0 = blockIdx.y * 48, d0 = blockIdx.x * 96;
    int tq = tid % 12, td = tid / 12;
    const float* Q = qt + (size_t)b * 480 * 300;
    const float* D = dg + (size_t)n * 960 * 300;
    float acc[4][4];
    #pragma unroll
    for (int i=0;i<4;i++)
        #pragma unroll
        for (int j=0;j<4;j++) acc[i][j] = 0.f;
    for (int c0 = 0; c0 < 300; c0 += 20){
        for (int idx = tid; idx < 48*20; idx += 288){
            int kk = idx % 20, r = idx / 20;
            sQ[kk][r] = Q[(size_t)(q0 + r)*300 + c0 + kk];
        }
        for (int idx = tid; idx < 96*20; idx += 288){
            int kk = idx % 20, r = idx / 20;
            sD[kk][r] = D[(size_t)(d0 + r)*300 + c0 + kk];
        }
        __syncthreads();
        #pragma unroll
        for (int kk=0; kk<20; kk++){
            float4 aq = *(const float4*)&sQ[kk][tq*4];
            float4 ad = *(const float4*)&sD[kk][td*4];
            float Aa[4] = {aq.x,aq.y,aq.z,aq.w};
            float Bb[4] = {ad.x,ad.y,ad.z,ad.w};
            #pragma unroll
            for (int i=0;i<4;i++)
                #pragma unroll
                for (int j=0;j<4;j++) acc[i][j] += Aa[i]*Bb[j];
        }
        __syncthreads();
    }
    float m = acc[0][0];
    #pragma unroll
    for (int i=0;i<4;i++)
        #pragma unroll
        for (int j=0;j<4;j++) m = fmaxf(m, acc[i][j]);
    if (tid < 16) pool[tid] = 0u;
    __syncthreads();
    int ci = tq/3, cj = td/6;
    atomicMax(&pool[ci*4 + cj], f2u(m));
    __syncthreads();
    if (tid < 16){
        int pi = tid >> 2, pj = tid & 3;
        float logit = u2f(pool[tid]) + bbp[0];
        int gi = blockIdx.y*4 + pi, gj = blockIdx.x*4 + pj;
        xout[((size_t)n*40 + gi)*40 + gj] = sigm(logit);
    }
}

// ---------------- 2D conv tower block (conv2x2 pad4 + sigmoid + pool47->40 + chmax) ----
__global__ void __launch_bounds__(256) convtower_kernel(
        const float* __restrict__ xin, const float* __restrict__ mw,
        const float* __restrict__ mb, float* __restrict__ xout){
    __shared__ float sx[40][40];
    __shared__ float swt[50][4];
    __shared__ float sb[50];
    int n = blockIdx.x, tid = threadIdx.x;
    for (int idx=tid; idx<1600; idx+=blockDim.x)
        sx[idx/40][idx%40] = xin[(size_t)n*1600 + idx];
    for (int idx=tid; idx<200; idx+=blockDim.x)
        swt[idx>>2][idx&3] = mw[idx];
    for (int idx=tid; idx<50; idx+=blockDim.x)
        sb[idx] = mb[idx];
    __syncthreads();
    for (int cell=tid; cell<1600; cell+=blockDim.x){
        int i = cell/40, j = cell%40;
        int hs = (i*47)/40,  he = ((i+1)*47 + 39)/40;
        int ws = (j*47)/40,  we = ((j+1)*47 + 39)/40;
        float m = -FLT_MAX;
        for (int h=hs; h<he; h++)
            for (int w=ws; w<we; w++){
                int r0=h-4, r1=h-3, c0=w-4, c1=w-3;
                float x00 = (r0>=0 && r0<40 && c0>=0 && c0<40) ? sx[r0][c0] : 0.f;
                float x01 = (r0>=0 && r0<40 && c1>=0 && c1<40) ? sx[r0][c1] : 0.f;
                float x10 = (r1>=0 && r1<40 && c0>=0 && c0<40) ? sx[r1][c0] : 0.f;
                float x11 = (r1>=0 && r1<40 && c1>=0 && c1<40) ? sx[r1][c1] : 0.f;
                for (int o=0;o<50;o++){
                    float l = fmaf(x00, swt[o][0],
                              fmaf(x01, swt[o][1],
                              fmaf(x10, swt[o][2],
                              fmaf(x11, swt[o][3], sb[o]))));
                    m = fmaxf(m, l);
                }
            }
        xout[(size_t)n*1600 + cell] = sigm(m);
    }
}

// ---------------- final logistic head ----------------
__global__ void __launch_bounds__(64) final_kernel(
        const float* __restrict__ feat, const float* __restrict__ lw,
        const float* __restrict__ lb, float* __restrict__ out){
    __shared__ float sh[40];
    int n = blockIdx.x, tid = threadIdx.x;
    if (tid < 40){
        float a = 0.f;
        const float* f = feat + (size_t)n*1600 + tid*40;
        for (int j=0;j<40;j++) a += f[j]*lw[j];
        sh[tid] = sigm(a + lb[0]);
    }
    __syncthreads();
    if (tid == 0){
        float a = 0.f;
        for (int i=0;i<40;i++) a += sh[i]*lw[i];
        out[n] = sigm(a + lb[0]);
    }
}

// ---------------- launch ----------------
extern "C" void kernel_launch(void* const* d_in, const int* in_sizes, int n_in,
                              void* d_out, int out_size){
    const float* query = (const float*)d_in[0];
    const float* pos   = (const float*)d_in[1];
    const float* neg   = (const float*)d_in[2];
    const float* qw1 = (const float*)d_in[3];  const float* qb1 = (const float*)d_in[4];
    const float* qw2 = (const float*)d_in[5];  const float* qb2 = (const float*)d_in[6];
    const float* qw3 = (const float*)d_in[7];  const float* qb3 = (const float*)d_in[8];
    const float* dw1 = (const float*)d_in[9];  const float* db1 = (const float*)d_in[10];
    const float* dw2 = (const float*)d_in[11]; const float* db2 = (const float*)d_in[12];
    const float* dw3 = (const float*)d_in[13]; const float* db3 = (const float*)d_in[14];
    const float* bw  = (const float*)d_in[15]; const float* bb  = (const float*)d_in[16];
    const float* mw1 = (const float*)d_in[17]; const float* mb1 = (const float*)d_in[18];
    const float* mw2 = (const float*)d_in[19]; const float* mb2 = (const float*)d_in[20];
    const float* mw3 = (const float*)d_in[21]; const float* mb3 = (const float*)d_in[22];
    const float* lw  = (const float*)d_in[23]; const float* lb  = (const float*)d_in[24];
    float* out = (float*)d_out;

    float *qpad, *qc1, *qp1p, *qc2, *qp2p, *qc3, *qg;
    float *dpad, *dc1, *dp1p, *dc2, *dp2p, *dc3, *dg;
    float *qt, *x0, *x1;
    cudaGetSymbolAddress((void**)&qpad, g_qpad);
    cudaGetSymbolAddress((void**)&qc1,  g_qc1);
    cudaGetSymbolAddress((void**)&qp1p, g_qp1p);
    cudaGetSymbolAddress((void**)&qc2,  g_qc2);
    cudaGetSymbolAddress((void**)&qp2p, g_qp2p);
    cudaGetSymbolAddress((void**)&qc3,  g_qc3);
    cudaGetSymbolAddress((void**)&qg,   g_qg);
    cudaGetSymbolAddress((void**)&dpad, g_dpad);
    cudaGetSymbolAddress((void**)&dc1,  g_dc1);
    cudaGetSymbolAddress((void**)&dp1p, g_dp1p);
    cudaGetSymbolAddress((void**)&dc2,  g_dc2);
    cudaGetSymbolAddress((void**)&dp2p, g_dp2p);
    cudaGetSymbolAddress((void**)&dc3,  g_dc3);
    cudaGetSymbolAddress((void**)&dg,   g_dg);
    cudaGetSymbolAddress((void**)&qt,   g_qt);
    cudaGetSymbolAddress((void**)&x0,   g_x0);
    cudaGetSymbolAddress((void**)&x1,   g_x1);

    const int QNS = 480*300;   // qg item stride
    const int DNS = 960*300;   // dg item stride

    // --- pads of raw inputs ---
    pad_rows_kernel<<<dim3((247*1024 + 255)/256, 16), 256>>>(qpad, query, 239, 1024, 239, 0);
    pad_docs_kernel<<<dim3((487*1024 + 255)/256, 80), 256>>>(dpad, pos, neg);

    // --- g0 (top-300 channels, ordered) ---
    kmax_last1024_kernel<<<dim3(239, 16), 256>>>(qpad, 247, qg, QNS);
    kmax_last1024_kernel<<<dim3(479, 80), 256>>>(dpad, 487, dg, DNS);

    // --- query tower ---
    conv1d_tanh_kernel<<<dim3(4,5,16), 256>>>(qpad, qw1, qb1, qc1, 247, 246, 1024);
    kmax_len_kernel<<<dim3(300,16), 256>>>(qc1, 246, 160, qg + 239*300, QNS);
    pad_rows_kernel<<<dim3((168*300 + 255)/256, 16), 256>>>(qp1p, qg, 160, 300, 480, 239);
    conv1d_tanh_kernel<<<dim3(3,5,16), 256>>>(qp1p, qw2, qb2, qc2, 168, 167, 300);
    kmax_len_kernel<<<dim3(300,16), 256>>>(qc2, 167, 80, qg + 399*300, QNS);
    pad_rows_kernel<<<dim3((88*300 + 255)/256, 16), 256>>>(qp2p, qg, 80, 300, 480, 399);
    conv1d_tanh_kernel<<<dim3(2,5,16), 256>>>(qp2p, qw3, qb3, qc3, 88, 87, 300);
    kmax_len_kernel<<<dim3(300,16), 256>>>(qc3, 87, 1, qg + 479*300, QNS);

    // --- doc tower ---
    conv1d_tanh_kernel<<<dim3(8,5,80), 256>>>(dpad, dw1, db1, dc1, 487, 486, 1024);
    kmax_len_kernel<<<dim3(300,80), 256>>>(dc1, 486, 320, dg + 479*300, DNS);
    pad_rows_kernel<<<dim3((328*300 + 255)/256, 80), 256>>>(dp1p, dg, 320, 300, 960, 479);
    conv1d_tanh_kernel<<<dim3(6,5,80), 256>>>(dp1p, dw2, db2, dc2, 328, 327, 300);
    kmax_len_kernel<<<dim3(300,80), 256>>>(dc2, 327, 160, dg + 799*300, DNS);
    pad_rows_kernel<<<dim3((168*300 + 255)/256, 80), 256>>>(dp2p, dg, 160, 300, 960, 799);
    conv1d_tanh_kernel<<<dim3(3,5,80), 256>>>(dp2p, dw3, db3, dc3, 168, 167, 300);
    kmax_len_kernel<<<dim3(300,80), 256>>>(dc3, 167, 1, dg + 959*300, DNS);

    // --- qt = qg @ bw ---
    sgemm_kernel<<<dim3(5, 120), 256>>>(qg, bw, qt, 16*480, 300, 300);

    // --- fused match GEMM + pool + sigmoid ---
    mpool_kernel<<<dim3(10, 10, 80), 288>>>(qt, dg, bb, x0);

    // --- conv2d tower x3 ---
    convtower_kernel<<<80, 256>>>(x0, mw1, mb1, x1);
    convtower_kernel<<<80, 256>>>(x1, mw2, mb2, x0);
    convtower_kernel<<<80, 256>>>(x0, mw3, mb3, x1);

    // --- head ---
    final_kernel<<<80, 64>>>(x1, lw, lb, out);
}

// round 3
// speedup vs baseline: 1.6036x; 1.6036x over previous
// multigrancnn GB300 — R3: radix-select top-k + f32x2 packed FMA GEMMs + k=1 fast path.
#include <cuda_runtime.h>
#include <math.h>
#include <float.h>

#define BT 256

// ---------------- static scratch ----------------
__device__ float g_qpad [16*247*1024];
__device__ float g_qc1  [16*246*300];
__device__ float g_qp1p [16*168*300];
__device__ float g_qc2  [16*167*300];
__device__ float g_qp2p [16*88*300];
__device__ float g_qc3  [16*87*300];
__device__ float g_qg   [16*480*300];
__device__ float g_dpad [80u*487*1024];
__device__ float g_dc1  [80u*486*300];
__device__ float g_dp1p [80u*328*300];
__device__ float g_dc2  [80u*327*300];
__device__ float g_dp2p [80u*168*300];
__device__ float g_dc3  [80u*167*300];
__device__ float g_dg   [80u*960*300];
__device__ float g_qt   [16*480*300];
__device__ float g_x0   [80*40*40];
__device__ float g_x1   [80*40*40];

// ---------------- helpers ----------------
__device__ __forceinline__ unsigned f2u(float f){
    unsigned u = __float_as_uint(f);
    return (u & 0x80000000u) ? ~u : (u | 0x80000000u);
}
__device__ __forceinline__ float u2f(unsigned u){
    unsigned b = (u & 0x80000000u) ? (u ^ 0x80000000u) : ~u;
    return __uint_as_float(b);
}
__device__ __forceinline__ float sigm(float x){ return 1.f/(1.f + expf(-x)); }

// f32x2 packed math
__device__ __forceinline__ unsigned long long pk2(float lo, float hi){
    unsigned long long r;
    asm("mov.b64 %0, {%1, %2};" : "=l"(r) : "f"(lo), "f"(hi));
    return r;
}
__device__ __forceinline__ float2 upk2(unsigned long long v){
    float2 r; asm("mov.b64 {%0, %1}, %2;" : "=f"(r.x), "=f"(r.y) : "l"(v));
    return r;
}
__device__ __forceinline__ void fma2(unsigned long long& d, unsigned long long a, unsigned long long b){
    asm("fma.rn.f32x2 %0, %1, %2, %0;" : "+l"(d) : "l"(a), "l"(b));
}

// exclusive scan across 256 threads (warp shfl based). sh: int[>=8]. 3 syncs.
__device__ __forceinline__ int block_scan_excl(int v, int tid, int* sh, int* total){
    int lane = tid & 31, w = tid >> 5;
    int x = v;
    #pragma unroll
    for (int off=1; off<32; off<<=1){
        int t = __shfl_up_sync(0xffffffffu, x, off);
        if (lane >= off) x += t;
    }
    if (lane == 31) sh[w] = x;
    __syncthreads();
    if (tid < 8){
        int t = sh[tid];
        #pragma unroll
        for (int off=1; off<8; off<<=1){
            int u = __shfl_up_sync(0xffu, t, off);
            if (tid >= off) t += u;
        }
        sh[tid] = t;
    }
    __syncthreads();
    int base = (w == 0) ? 0 : sh[w-1];
    *total = sh[7];
    int res = base + x - v;
    __syncthreads();
    return res;
}

// top-k of skey[0..n), order preserved, ties by lowest index (lax.top_k semantics).
// 256-bucket radix select (4 passes) then compaction.
// hist: int[256], sws: int[257]. BT threads.
__device__ void topk_select(const unsigned* skey, int n, int k, short* out_idx,
                            int* hist, int* sws, int tid){
    unsigned prefix = 0;
    int kr = k;
    #pragma unroll
    for (int pass=0; pass<4; pass++){
        int shift = 24 - 8*pass;
        for (int i=tid; i<256; i+=BT) hist[i] = 0;
        __syncthreads();
        if (pass == 0){
            for (int i=tid; i<n; i+=BT) atomicAdd(&hist[skey[i] >> 24], 1);
        } else {
            int hs = shift + 8;
            for (int i=tid; i<n; i+=BT){
                unsigned v = skey[i];
                if ((v >> hs) == prefix) atomicAdd(&hist[(v >> shift) & 255u], 1);
            }
        }
        __syncthreads();
        // suffix-inclusive cumulative into sws (warp 0 only)
        if (tid < 32){
            int base = tid * 8;
            int h[8]; int tot = 0;
            #pragma unroll
            for (int j=0; j<8; j++){ h[j] = hist[base+j]; tot += h[j]; }
            int run = tot;
            #pragma unroll
            for (int off=1; off<32; off<<=1){
                int t = __shfl_down_sync(0xffffffffu, run, off);
                if (tid + off < 32) run += t;
            }
            int acc = run - tot;   // sum of lanes above
            #pragma unroll
            for (int j=7; j>=0; j--){ acc += h[j]; sws[base+j] = acc; }
        }
        __syncthreads();
        int cum  = sws[tid];
        int cumn = (tid < 255) ? sws[tid+1] : 0;
        if (cum >= kr && cumn < kr){
            sws[256] = tid;   // selected digit (unique)
            hist[0]  = cumn;  // count strictly above digit (within prefix)
        }
        __syncthreads();
        int d = sws[256];
        kr -= hist[0];
        prefix = (prefix << 8) | (unsigned)d;
        __syncthreads();
    }
    unsigned T = prefix;
    int m_eq = kr;   // ties at T to keep (lowest indices)

    int ipt = (n + BT - 1)/BT;
    int beg = tid*ipt; if (beg > n) beg = n;
    int end = beg + ipt; if (end > n) end = n;

    int ceq = 0;
    for (int i=beg; i<end; i++) ceq += (skey[i] == T);
    int tot;
    int eq_base = block_scan_excl(ceq, tid, sws, &tot);

    int csel = 0;
    { int eqr = eq_base;
      for (int i=beg; i<end; i++){
          unsigned v = skey[i]; int e = (v == T);
          csel += (v > T) || (e && eqr < m_eq);
          eqr += e;
      } }
    int out_base = block_scan_excl(csel, tid, sws, &tot);
    { int eqr = eq_base, p = out_base;
      for (int i=beg; i<end; i++){
          unsigned v = skey[i]; int e = (v == T);
          if ((v > T) || (e && eqr < m_eq)) out_idx[p++] = (short)i;
          eqr += e;
      } }
    __syncthreads();
}

// ---------------- pad kernels ----------------
__global__ void __launch_bounds__(256) pad_rows_kernel(
        float* dst, const float* __restrict__ src,
        int L, int C, int srcRowsPerItem, int srcRowOffset){
    int n = blockIdx.y;
    int idx = blockIdx.x*blockDim.x + threadIdx.x;
    int LP = L + 8;
    if (idx >= LP*C) return;
    int l = idx / C, c = idx - l*C;
    float v = 0.f;
    if (l >= 4 && l < 4+L)
        v = src[((size_t)n*srcRowsPerItem + srcRowOffset + (l-4))*C + c];
    dst[(size_t)n*LP*C + idx] = v;
}

__global__ void __launch_bounds__(256) pad_docs_kernel(
        float* dst, const float* __restrict__ pos, const float* __restrict__ neg){
    const int LP = 487, C = 1024, L = 479;
    int n = blockIdx.y;
    int idx = blockIdx.x*blockDim.x + threadIdx.x;
    if (idx >= LP*C) return;
    int l = idx / C, c = idx - l*C;
    float v = 0.f;
    if (l >= 4 && l < 4+L){
        int s = n >> 4, b = n & 15;
        const float* src = (s==0) ? (pos + (size_t)b*L*C)
                                  : (neg + ((size_t)(s-1)*16 + b)*L*C);
        v = src[(size_t)(l-4)*C + c];
    }
    dst[(size_t)n*LP*C + idx] = v;
}

// ---------------- kmax over channel axis (1024 -> 300) ----------------
__global__ void __launch_bounds__(256) kmax_last1024_kernel(
        const float* __restrict__ src, int Lpad,
        float* __restrict__ dst, int dstNstride){
    __shared__ unsigned skey[1024];
    __shared__ int      hist[256];
    __shared__ int      sws[257];
    __shared__ short    sidx[300];
    int tid = threadIdx.x;
    int l = blockIdx.x, n = blockIdx.y;
    const float* row = src + ((size_t)n*Lpad + 4 + l)*1024;
    for (int i=tid; i<1024; i+=BT) skey[i] = f2u(row[i]);
    __syncthreads();
    topk_select(skey, 1024, 300, sidx, hist, sws, tid);
    float* orow = dst + (size_t)n*dstNstride + (size_t)l*300;
    for (int j=tid; j<300; j+=BT) orow[j] = u2f(skey[sidx[j]]);
}

// ---------------- kmax over length axis (k >= 2) ----------------
__global__ void __launch_bounds__(256) kmax_len_kernel(
        const float* __restrict__ src, int Lin, int k,
        float* __restrict__ dstBase, int dstNstride){
    __shared__ unsigned skey[512];
    __shared__ int      hist[256];
    __shared__ int      sws[257];
    __shared__ short    sidx[320];
    int tid = threadIdx.x;
    int o = blockIdx.x, n = blockIdx.y;
    for (int l=tid; l<Lin; l+=BT)
        skey[l] = f2u(src[((size_t)n*Lin + l)*300 + o]);
    __syncthreads();
    topk_select(skey, Lin, k, sidx, hist, sws, tid);
    float* dn = dstBase + (size_t)n*dstNstride;
    for (int j=tid; j<k; j+=BT)
        dn[(size_t)j*300 + o] = u2f(skey[sidx[j]]);
}

// ---------------- k=1: plain max over length, warp per output channel -------
__global__ void __launch_bounds__(256) maxlen_kernel(
        const float* __restrict__ src, int Lin,
        float* __restrict__ dstBase, int dstNstride){
    int w = threadIdx.x >> 5, lane = threadIdx.x & 31;
    int o = blockIdx.x*8 + w;
    int n = blockIdx.y;
    if (o >= 300) return;
    float m = -FLT_MAX;
    for (int l=lane; l<Lin; l+=32)
        m = fmaxf(m, src[((size_t)n*Lin + l)*300 + o]);
    #pragma unroll
    for (int off=16; off; off>>=1)
        m = fmaxf(m, __shfl_down_sync(0xffffffffu, m, off));
    if (lane == 0) dstBase[(size_t)n*dstNstride + o] = m;
}

// ---------------- conv1d(k=2)+tanh as GEMM (f32x2) ----------------
__global__ void __launch_bounds__(256) conv1d_tanh_kernel(
        const float* __restrict__ in, const float* __restrict__ w,
        const float* __restrict__ bias, float* __restrict__ out,
        int Lpad, int Lout, int Cin){
    __shared__ float sA[16][68];       // [kk][l], 65 l's used
    __shared__ float sW[2][16][68];    // [tap][kk][o]
    int tid = threadIdx.x;
    int tx = tid & 15, ty = tid >> 4;
    int l0 = blockIdx.x * 64;
    int o0 = blockIdx.y * 64;
    int n  = blockIdx.z;
    const float* inN = in + (size_t)n * Lpad * Cin;
    unsigned long long acc2[4][2];
    #pragma unroll
    for (int i=0;i<4;i++){ acc2[i][0]=0ull; acc2[i][1]=0ull; }
    int row = ty*4, col = tx*4;
    for (int c0 = 0; c0 < Cin; c0 += 16){
        for (int idx = tid; idx < 65*16; idx += BT){
            int kk = idx & 15, l = idx >> 4;
            int gl = l0 + l, gc = c0 + kk;
            float v = 0.f;
            if (gl < Lpad && gc < Cin) v = inN[(size_t)gl*Cin + gc];
            sA[kk][l] = v;
        }
        for (int idx = tid; idx < 2048; idx += BT){
            int t = idx & 1, kk = (idx >> 1) & 15, o = idx >> 5;
            int go = o0 + o, gc = c0 + kk;
            float v = 0.f;
            if (go < 300 && gc < Cin) v = w[((size_t)go*Cin + gc)*2 + t];
            sW[t][kk][o] = v;
        }
        __syncthreads();
        #pragma unroll
        for (int kk=0; kk<16; kk++){
            float4 a4 = *(const float4*)&sA[kk][row];
            float  a5 = sA[kk][row+4];
            ulonglong2 b0 = *(const ulonglong2*)&sW[0][kk][col];
            ulonglong2 b1 = *(const ulonglong2*)&sW[1][kk][col];
            unsigned long long d0 = pk2(a4.x,a4.x);
            unsigned long long d1 = pk2(a4.y,a4.y);
            unsigned long long d2 = pk2(a4.z,a4.z);
            unsigned long long d3 = pk2(a4.w,a4.w);
            unsigned long long d4 = pk2(a5,a5);
            fma2(acc2[0][0], d0, b0.x); fma2(acc2[0][1], d0, b0.y);
            fma2(acc2[0][0], d1, b1.x); fma2(acc2[0][1], d1, b1.y);
            fma2(acc2[1][0], d1, b0.x); fma2(acc2[1][1], d1, b0.y);
            fma2(acc2[1][0], d2, b1.x); fma2(acc2[1][1], d2, b1.y);
            fma2(acc2[2][0], d2, b0.x); fma2(acc2[2][1], d2, b0.y);
            fma2(acc2[2][0], d3, b1.x); fma2(acc2[2][1], d3, b1.y);
            fma2(acc2[3][0], d3, b0.x); fma2(acc2[3][1], d3, b0.y);
            fma2(acc2[3][0], d4, b1.x); fma2(acc2[3][1], d4, b1.y);
        }
        __syncthreads();
    }
    #pragma unroll
    for (int i=0;i<4;i++){
        int gl = l0 + row + i;
        if (gl >= Lout) continue;
        #pragma unroll
        for (int j2=0;j2<2;j2++){
            float2 v = upk2(acc2[i][j2]);
            int go = o0 + col + 2*j2;
            if (go < 300)   out[((size_t)n*Lout + gl)*300 + go]   = tanhf(v.x + bias[go]);
            if (go+1 < 300) out[((size_t)n*Lout + gl)*300 + go+1] = tanhf(v.y + bias[go+1]);
        }
    }
}

// ---------------- generic SGEMM: C(M,N) = A(M,K) * B(K,N) (f32x2) -----------
__global__ void __launch_bounds__(256) sgemm_kernel(
        const float* __restrict__ A, const float* __restrict__ B,
        float* __restrict__ C, int M, int N, int K){
    __shared__ float sA[16][68];
    __shared__ float sB[16][68];
    int tid = threadIdx.x;
    int tx = tid & 15, ty = tid >> 4;
    int n0 = blockIdx.x * 64, m0 = blockIdx.y * 64;
    unsigned long long acc2[4][2];
    #pragma unroll
    for (int i=0;i<4;i++){ acc2[i][0]=0ull; acc2[i][1]=0ull; }
    int row = ty*4, col = tx*4;
    for (int k0 = 0; k0 < K; k0 += 16){
        for (int idx = tid; idx < 1024; idx += BT){
            int kk = idx & 15, m = idx >> 4;
            int gm = m0 + m, gk = k0 + kk;
            sA[kk][m] = (gm < M && gk < K) ? A[(size_t)gm*K + gk] : 0.f;
        }
        for (int idx = tid; idx < 1024; idx += BT){
            int nn = idx & 63, kk = idx >> 6;
            int gn = n0 + nn, gk = k0 + kk;
            sB[kk][nn] = (gn < N && gk < K) ? B[(size_t)gk*N + gn] : 0.f;
        }
        __syncthreads();
        #pragma unroll
        for (int kk=0; kk<16; kk++){
            float4 a4 = *(const float4*)&sA[kk][row];
            ulonglong2 b2 = *(const ulonglong2*)&sB[kk][col];
            unsigned long long d0 = pk2(a4.x,a4.x);
            unsigned long long d1 = pk2(a4.y,a4.y);
            unsigned long long d2 = pk2(a4.z,a4.z);
            unsigned long long d3 = pk2(a4.w,a4.w);
            fma2(acc2[0][0], d0, b2.x); fma2(acc2[0][1], d0, b2.y);
            fma2(acc2[1][0], d1, b2.x); fma2(acc2[1][1], d1, b2.y);
            fma2(acc2[2][0], d2, b2.x); fma2(acc2[2][1], d2, b2.y);
            fma2(acc2[3][0], d3, b2.x); fma2(acc2[3][1], d3, b2.y);
        }
        __syncthreads();
    }
    #pragma unroll
    for (int i=0;i<4;i++){
        int gm = m0 + row + i;
        if (gm >= M) continue;
        #pragma unroll
        for (int j2=0;j2<2;j2++){
            float2 v = upk2(acc2[i][j2]);
            int gn = n0 + col + 2*j2;
            if (gn < N)   C[(size_t)gm*N + gn]   = v.x;
            if (gn+1 < N) C[(size_t)gm*N + gn+1] = v.y;
        }
    }
}

// ---------------- fused match GEMM + 12x24 max-pool + sigmoid (f32x2) -------
__global__ void __launch_bounds__(288) mpool_kernel(
        const float* __restrict__ qt, const float* __restrict__ dg,
        const float* __restrict__ bbp, float* __restrict__ xout){
    __shared__ float sQ[20][52];
    __shared__ float sD[20][100];
    __shared__ unsigned pool[16];
    int tid = threadIdx.x;
    int n = blockIdx.z, b = n & 15;
    int q0 = blockIdx.y * 48, d0 = blockIdx.x * 96;
    int tq = tid % 12, td = tid / 12;
    const float* Q = qt + (size_t)b * 480 * 300;
    const float* D = dg + (size_t)n * 960 * 300;
    unsigned long long acc2[4][2];
    #pragma unroll
    for (int i=0;i<4;i++){ acc2[i][0]=0ull; acc2[i][1]=0ull; }
    for (int c0 = 0; c0 < 300; c0 += 20){
        for (int idx = tid; idx < 48*20; idx += 288){
            int kk = idx % 20, r = idx / 20;
            sQ[kk][r] = Q[(size_t)(q0 + r)*300 + c0 + kk];
        }
        for (int idx = tid; idx < 96*20; idx += 288){
            int kk = idx % 20, r = idx / 20;
            sD[kk][r] = D[(size_t)(d0 + r)*300 + c0 + kk];
        }
        __syncthreads();
        #pragma unroll
        for (int kk=0; kk<20; kk++){
            float4 aq = *(const float4*)&sQ[kk][tq*4];
            ulonglong2 b2 = *(const ulonglong2*)&sD[kk][td*4];
            unsigned long long d0r = pk2(aq.x,aq.x);
            unsigned long long d1r = pk2(aq.y,aq.y);
            unsigned long long d2r = pk2(aq.z,aq.z);
            unsigned long long d3r = pk2(aq.w,aq.w);
            fma2(acc2[0][0], d0r, b2.x); fma2(acc2[0][1], d0r, b2.y);
            fma2(acc2[1][0], d1r, b2.x); fma2(acc2[1][1], d1r, b2.y);
            fma2(acc2[2][0], d2r, b2.x); fma2(acc2[2][1], d2r, b2.y);
            fma2(acc2[3][0], d3r, b2.x); fma2(acc2[3][1], d3r, b2.y);
        }
        __syncthreads();
    }
    float m = -FLT_MAX;
    #pragma unroll
    for (int i=0;i<4;i++)
        #pragma unroll
        for (int j2=0;j2<2;j2++){
            float2 v = upk2(acc2[i][j2]);
            m = fmaxf(m, fmaxf(v.x, v.y));
        }
    if (tid < 16) pool[tid] = 0u;
    __syncthreads();
    int ci = tq/3, cj = td/6;
    atomicMax(&pool[ci*4 + cj], f2u(m));
    __syncthreads();
    if (tid < 16){
        int pi = tid >> 2, pj = tid & 3;
        float logit = u2f(pool[tid]) + bbp[0];
        int gi = blockIdx.y*4 + pi, gj = blockIdx.x*4 + pj;
        xout[((size_t)n*40 + gi)*40 + gj] = sigm(logit);
    }
}

// ---------------- 2D conv tower block ----------------
__global__ void __launch_bounds__(256) convtower_kernel(
        const float* __restrict__ xin, const float* __restrict__ mw,
        const float* __restrict__ mb, float* __restrict__ xout){
    __shared__ float sx[40][40];
    __shared__ float swt[50][4];
    __shared__ float sb[50];
    int n = blockIdx.x, tid = threadIdx.x;
    for (int idx=tid; idx<1600; idx+=blockDim.x)
        sx[idx/40][idx%40] = xin[(size_t)n*1600 + idx];
    for (int idx=tid; idx<200; idx+=blockDim.x)
        swt[idx>>2][idx&3] = mw[idx];
    for (int idx=tid; idx<50; idx+=blockDim.x)
        sb[idx] = mb[idx];
    __syncthreads();
    for (int cell=tid; cell<1600; cell+=blockDim.x){
        int i = cell/40, j = cell%40;
        int hs = (i*47)/40,  he = ((i+1)*47 + 39)/40;
        int ws = (j*47)/40,  we = ((j+1)*47 + 39)/40;
        float m = -FLT_MAX;
        for (int h=hs; h<he; h++)
            for (int w=ws; w<we; w++){
                int r0=h-4, r1=h-3, c0=w-4, c1=w-3;
                float x00 = (r0>=0 && r0<40 && c0>=0 && c0<40) ? sx[r0][c0] : 0.f;
                float x01 = (r0>=0 && r0<40 && c1>=0 && c1<40) ? sx[r0][c1] : 0.f;
                float x10 = (r1>=0 && r1<40 && c0>=0 && c0<40) ? sx[r1][c0] : 0.f;
                float x11 = (r1>=0 && r1<40 && c1>=0 && c1<40) ? sx[r1][c1] : 0.f;
                for (int o=0;o<50;o++){
                    float l = fmaf(x00, swt[o][0],
                              fmaf(x01, swt[o][1],
                              fmaf(x10, swt[o][2],
                              fmaf(x11, swt[o][3], sb[o]))));
                    m = fmaxf(m, l);
                }
            }
        xout[(size_t)n*1600 + cell] = sigm(m);
    }
}

// ---------------- final logistic head ----------------
__global__ void __launch_bounds__(64) final_kernel(
        const float* __restrict__ feat, const float* __restrict__ lw,
        const float* __restrict__ lb, float* __restrict__ out){
    __shared__ float sh[40];
    int n = blockIdx.x, tid = threadIdx.x;
    if (tid < 40){
        float a = 0.f;
        const float* f = feat + (size_t)n*1600 + tid*40;
        for (int j=0;j<40;j++) a += f[j]*lw[j];
        sh[tid] = sigm(a + lb[0]);
    }
    __syncthreads();
    if (tid == 0){
        float a = 0.f;
        for (int i=0;i<40;i++) a += sh[i]*lw[i];
        out[n] = sigm(a + lb[0]);
    }
}

// ---------------- launch ----------------
extern "C" void kernel_launch(void* const* d_in, const int* in_sizes, int n_in,
                              void* d_out, int out_size){
    const float* query = (const float*)d_in[0];
    const float* pos   = (const float*)d_in[1];
    const float* neg   = (const float*)d_in[2];
    const float* qw1 = (const float*)d_in[3];  const float* qb1 = (const float*)d_in[4];
    const float* qw2 = (const float*)d_in[5];  const float* qb2 = (const float*)d_in[6];
    const float* qw3 = (const float*)d_in[7];  const float* qb3 = (const float*)d_in[8];
    const float* dw1 = (const float*)d_in[9];  const float* db1 = (const float*)d_in[10];
    const float* dw2 = (const float*)d_in[11]; const float* db2 = (const float*)d_in[12];
    const float* dw3 = (const float*)d_in[13]; const float* db3 = (const float*)d_in[14];
    const float* bw  = (const float*)d_in[15]; const float* bb  = (const float*)d_in[16];
    const float* mw1 = (const float*)d_in[17]; const float* mb1 = (const float*)d_in[18];
    const float* mw2 = (const float*)d_in[19]; const float* mb2 = (const float*)d_in[20];
    const float* mw3 = (const float*)d_in[21]; const float* mb3 = (const float*)d_in[22];
    const float* lw  = (const float*)d_in[23]; const float* lb  = (const float*)d_in[24];
    float* out = (float*)d_out;

    float *qpad, *qc1, *qp1p, *qc2, *qp2p, *qc3, *qg;
    float *dpad, *dc1, *dp1p, *dc2, *dp2p, *dc3, *dg;
    float *qt, *x0, *x1;
    cudaGetSymbolAddress((void**)&qpad, g_qpad);
    cudaGetSymbolAddress((void**)&qc1,  g_qc1);
    cudaGetSymbolAddress((void**)&qp1p, g_qp1p);
    cudaGetSymbolAddress((void**)&qc2,  g_qc2);
    cudaGetSymbolAddress((void**)&qp2p, g_qp2p);
    cudaGetSymbolAddress((void**)&qc3,  g_qc3);
    cudaGetSymbolAddress((void**)&qg,   g_qg);
    cudaGetSymbolAddress((void**)&dpad, g_dpad);
    cudaGetSymbolAddress((void**)&dc1,  g_dc1);
    cudaGetSymbolAddress((void**)&dp1p, g_dp1p);
    cudaGetSymbolAddress((void**)&dc2,  g_dc2);
    cudaGetSymbolAddress((void**)&dp2p, g_dp2p);
    cudaGetSymbolAddress((void**)&dc3,  g_dc3);
    cudaGetSymbolAddress((void**)&dg,   g_dg);
    cudaGetSymbolAddress((void**)&qt,   g_qt);
    cudaGetSymbolAddress((void**)&x0,   g_x0);
    cudaGetSymbolAddress((void**)&x1,   g_x1);

    const int QNS = 480*300;
    const int DNS = 960*300;

    pad_rows_kernel<<<dim3((247*1024 + 255)/256, 16), 256>>>(qpad, query, 239, 1024, 239, 0);
    pad_docs_kernel<<<dim3((487*1024 + 255)/256, 80), 256>>>(dpad, pos, neg);

    kmax_last1024_kernel<<<dim3(239, 16), 256>>>(qpad, 247, qg, QNS);
    kmax_last1024_kernel<<<dim3(479, 80), 256>>>(dpad, 487, dg, DNS);

    conv1d_tanh_kernel<<<dim3(4,5,16), 256>>>(qpad, qw1, qb1, qc1, 247, 246, 1024);
    kmax_len_kernel<<<dim3(300,16), 256>>>(qc1, 246, 160, qg + 239*300, QNS);
    pad_rows_kernel<<<dim3((168*300 + 255)/256, 16), 256>>>(qp1p, qg, 160, 300, 480, 239);
    conv1d_tanh_kernel<<<dim3(3,5,16), 256>>>(qp1p, qw2, qb2, qc2, 168, 167, 300);
    kmax_len_kernel<<<dim3(300,16), 256>>>(qc2, 167, 80, qg + 399*300, QNS);
    pad_rows_kernel<<<dim3((88*300 + 255)/256, 16), 256>>>(qp2p, qg, 80, 300, 480, 399);
    conv1d_tanh_kernel<<<dim3(2,5,16), 256>>>(qp2p, qw3, qb3, qc3, 88, 87, 300);
    maxlen_kernel<<<dim3(38,16), 256>>>(qc3, 87, qg + 479*300, QNS);

    conv1d_tanh_kernel<<<dim3(8,5,80), 256>>>(dpad, dw1, db1, dc1, 487, 486, 1024);
    kmax_len_kernel<<<dim3(300,80), 256>>>(dc1, 486, 320, dg + 479*300, DNS);
    pad_rows_kernel<<<dim3((328*300 + 255)/256, 80), 256>>>(dp1p, dg, 320, 300, 960, 479);
    conv1d_tanh_kernel<<<dim3(6,5,80), 256>>>(dp1p, dw2, db2, dc2, 328, 327, 300);
    kmax_len_kernel<<<dim3(300,80), 256>>>(dc2, 327, 160, dg + 799*300, DNS);
    pad_rows_kernel<<<dim3((168*300 + 255)/256, 80), 256>>>(dp2p, dg, 160, 300, 960, 799);
    conv1d_tanh_kernel<<<dim3(3,5,80), 256>>>(dp2p, dw3, db3, dc3, 168, 167, 300);
    maxlen_kernel<<<dim3(38,80), 256>>>(dc3, 167, dg + 959*300, DNS);

    sgemm_kernel<<<dim3(5, 120), 256>>>(qg, bw, qt, 16*480, 300, 300);

    mpool_kernel<<<dim3(10, 10, 80), 288>>>(qt, dg, bb, x0);

    convtower_kernel<<<80, 256>>>(x0, mw1, mb1, x1);
    convtower_kernel<<<80, 256>>>(x1, mw2, mb2, x0);
    convtower_kernel<<<80, 256>>>(x0, mw3, mb3, x1);

    final_kernel<<<80, 64>>>(x1, lw, lb, out);
}

// round 6
// speedup vs baseline: 2.0965x; 1.3074x over previous
// multigrancnn GB300 — R6: conv1d via mma.sync bf16x3 (arch-generic HMMA; tcgen05
// unavailable: harness PTX targets compute_103). Transposed coalesced kmax_len.
#include <cuda_runtime.h>
#include <cuda_bf16.h>
#include <cstdint>
#include <math.h>
#include <float.h>

#define BT 256

// ---------------- static scratch ----------------
__device__ __align__(16) float g_qpad [16*247*1024];
__device__ __align__(16) float g_qc1  [16*246*300];
__device__ __align__(16) float g_qp1p [16*168*300];
__device__ __align__(16) float g_qc2  [16*167*300];
__device__ __align__(16) float g_qp2p [16*88*300];
__device__ __align__(16) float g_qc3  [16*87*300];
__device__ __align__(16) float g_qg   [16*480*300];
__device__ __align__(16) float g_dpad [80u*487*1024];
__device__ __align__(16) float g_dc1  [80u*486*300];
__device__ __align__(16) float g_dp1p [80u*328*300];
__device__ __align__(16) float g_dc2  [80u*327*300];
__device__ __align__(16) float g_dp2p [80u*168*300];
__device__ __align__(16) float g_dc3  [80u*167*300];
__device__ __align__(16) float g_dg   [80u*960*300];
__device__ __align__(16) float g_qt   [16*480*300];
__device__ __align__(16) float g_x0   [80*40*40];
__device__ __align__(16) float g_x1   [80*40*40];

// ---------------- helpers ----------------
__device__ __forceinline__ unsigned f2u(float f){
    unsigned u = __float_as_uint(f);
    return (u & 0x80000000u) ? ~u : (u | 0x80000000u);
}
__device__ __forceinline__ float u2f(unsigned u){
    unsigned b = (u & 0x80000000u) ? (u ^ 0x80000000u) : ~u;
    return __uint_as_float(b);
}
__device__ __forceinline__ float sigm(float x){ return 1.f/(1.f + expf(-x)); }

// f32x2 packed math
__device__ __forceinline__ unsigned long long pk2(float lo, float hi){
    unsigned long long r;
    asm("mov.b64 %0, {%1, %2};" : "=l"(r) : "f"(lo), "f"(hi));
    return r;
}
__device__ __forceinline__ float2 upk2(unsigned long long v){
    float2 r; asm("mov.b64 {%0, %1}, %2;" : "=f"(r.x), "=f"(r.y) : "l"(v));
    return r;
}
__device__ __forceinline__ void fma2(unsigned long long& d, unsigned long long a, unsigned long long b){
    asm("fma.rn.f32x2 %0, %1, %2, %0;" : "+l"(d) : "l"(a), "l"(b));
}

// ---------------- mma.sync primitives (arch-generic) ----------------
__device__ __forceinline__ uint32_t smem_u32(const void* p){
    uint32_t a;
    asm("{ .reg .u64 t; cvta.to.shared.u64 t, %1; cvt.u32.u64 %0, t; }" : "=r"(a) : "l"(p));
    return a;
}
__device__ __forceinline__ void ldmx4(uint32_t* r, uint32_t addr){
    asm volatile("ldmatrix.sync.aligned.m8n8.x4.shared.b16 {%0,%1,%2,%3}, [%4];"
                 : "=r"(r[0]), "=r"(r[1]), "=r"(r[2]), "=r"(r[3]) : "r"(addr));
}
__device__ __forceinline__ void ldmx2(uint32_t* r, uint32_t addr){
    asm volatile("ldmatrix.sync.aligned.m8n8.x2.shared.b16 {%0,%1}, [%2];"
                 : "=r"(r[0]), "=r"(r[1]) : "r"(addr));
}
__device__ __forceinline__ void mma_bf16(float* c, const uint32_t* a, const uint32_t* b){
    asm volatile(
        "mma.sync.aligned.m16n8k16.row.col.f32.bf16.bf16.f32 "
        "{%0,%1,%2,%3}, {%4,%5,%6,%7}, {%8,%9}, {%0,%1,%2,%3};"
        : "+f"(c[0]), "+f"(c[1]), "+f"(c[2]), "+f"(c[3])
        : "r"(a[0]), "r"(a[1]), "r"(a[2]), "r"(a[3]), "r"(b[0]), "r"(b[1]));
}

// hi/lo bf16 split of 8 floats -> two uint4
__device__ __forceinline__ void hilo_pack(const float* v, uint4& uh, uint4& ul){
    unsigned hs[8], ls[8];
    #pragma unroll
    for (int e=0;e<8;e++){
        float f = v[e];
        __nv_bfloat16 h = __float2bfloat16(f);
        float hf = __bfloat162float(h);
        __nv_bfloat16 l = __float2bfloat16(f - hf);
        hs[e] = (unsigned)__bfloat16_as_ushort(h);
        ls[e] = (unsigned)__bfloat16_as_ushort(l);
    }
    uh.x = hs[0] | (hs[1]<<16); uh.y = hs[2] | (hs[3]<<16);
    uh.z = hs[4] | (hs[5]<<16); uh.w = hs[6] | (hs[7]<<16);
    ul.x = ls[0] | (ls[1]<<16); ul.y = ls[2] | (ls[3]<<16);
    ul.z = ls[4] | (ls[5]<<16); ul.w = ls[6] | (ls[7]<<16);
}

// ---------------- conv1d(k=2)+tanh via mma.sync bf16x3 ----------------
// out[n][l][o] = tanh( sum_j A[l][j] * W[o][j] + bias[o] ),  A[l][j]=in[l+(j&1)][j>>1]
// CTA: 128(L) x 64(O). 8 warps = 4(m) x 2(n). warp: 32x32 = 2 m-tiles x 4 n-tiles.
#define CPAD 72                     // bf16 row pitch (pad 64 -> 72)
#define OFF_AH 0
#define OFF_AL (128*CPAD*2)         // 18432
#define OFF_BH (2*128*CPAD*2)       // 36864
#define OFF_BL (2*128*CPAD*2 + 64*CPAD*2)  // 46080
#define CONV_SMEM_SZ (2*128*CPAD*2 + 2*64*CPAD*2)  // 55296

__global__ void __launch_bounds__(256) conv1d_mma_kernel(
        const float* __restrict__ in, const float* __restrict__ w,
        const float* __restrict__ bias, float* __restrict__ out,
        int Lpad, int Lout, int Cin){
    extern __shared__ __align__(16) char smem[];
    const int K2 = 2*Cin;
    const int nch = (K2 + 63)/64;
    uint32_t sb = smem_u32(smem);
    int tid = threadIdx.x, wid = tid>>5, lane = tid&31;
    int wm = wid & 3, wn = wid >> 2;           // warp grid 4(m) x 2(n)
    int l0 = blockIdx.x*128, n0 = blockIdx.y*64, nb = blockIdx.z;
    const float* inN = in + (size_t)nb*Lpad*Cin;

    float acc[2][4][4];
    #pragma unroll
    for (int mt=0; mt<2; mt++)
        #pragma unroll
        for (int nt=0; nt<4; nt++)
            #pragma unroll
            for (int e=0; e<4; e++) acc[mt][nt][e] = 0.f;

    // ldmatrix per-lane addresses (fixed row/col adds)
    int a_row_add = (lane & 7) + ((lane >> 3) & 1)*8;
    int a_col_add = ((lane >> 4) & 1)*8;
    int b_row_add = (lane & 7);
    int b_col_add = ((lane >> 3) & 1)*8;   // lanes >=16 replicate (unused)

    for (int ch=0; ch<nch; ch++){
        int jc = ch*64;
        // ---- A tile: 128 rows x 8 granules of 8 ----
        #pragma unroll
        for (int it=0; it<4; it++){
            int task = tid + it*256;
            int r = task >> 3, g = task & 7;
            int j0 = jc + g*8;
            int gl = l0 + r;
            float4 fa = {0,0,0,0}, fb = {0,0,0,0};
            if (j0 < K2){
                int c0 = j0 >> 1;
                if (gl   < Lpad) fa = *(const float4*)&inN[(size_t)gl*Cin + c0];
                if (gl+1 < Lpad) fb = *(const float4*)&inN[(size_t)(gl+1)*Cin + c0];
            }
            float v[8] = {fa.x,fb.x,fa.y,fb.y,fa.z,fb.z,fa.w,fb.w};
            uint4 uh, ul;
            hilo_pack(v, uh, ul);
            uint32_t boff = (uint32_t)(r*CPAD + g*8)*2;
            *(uint4*)(smem + OFF_AH + boff) = uh;
            *(uint4*)(smem + OFF_AL + boff) = ul;
        }
        // ---- B tile: 64 o-rows x 8 granules ----
        #pragma unroll
        for (int it=0; it<2; it++){
            int task = tid + it*256;
            int r = task >> 3, g = task & 7;
            int j0 = jc + g*8;
            int o = n0 + r;
            float4 fa = {0,0,0,0}, fb = {0,0,0,0};
            if (j0 < K2 && o < 300){
                const float* wr = w + (size_t)o*K2 + j0;
                fa = *(const float4*)wr;
                fb = *(const float4*)(wr+4);
            }
            float v[8] = {fa.x,fa.y,fa.z,fa.w,fb.x,fb.y,fb.z,fb.w};
            uint4 uh, ul;
            hilo_pack(v, uh, ul);
            uint32_t boff = (uint32_t)(r*CPAD + g*8)*2;
            *(uint4*)(smem + OFF_BH + boff) = uh;
            *(uint4*)(smem + OFF_BL + boff) = ul;
        }
        __syncthreads();
        // ---- 4 k16 steps ----
        #pragma unroll
        for (int ks=0; ks<4; ks++){
            uint32_t ah[2][4], al[2][4], bh[4][2], bl[4][2];
            #pragma unroll
            for (int mt=0; mt<2; mt++){
                int row = wm*32 + mt*16 + a_row_add;
                uint32_t off = (uint32_t)(row*CPAD + ks*16 + a_col_add)*2;
                ldmx4(ah[mt], sb + OFF_AH + off);
                ldmx4(al[mt], sb + OFF_AL + off);
            }
            #pragma unroll
            for (int nt=0; nt<4; nt++){
                int row = wn*32 + nt*8 + b_row_add;
                uint32_t off = (uint32_t)(row*CPAD + ks*16 + b_col_add)*2;
                ldmx2(bh[nt], sb + OFF_BH + off);
                ldmx2(bl[nt], sb + OFF_BL + off);
            }
            #pragma unroll
            for (int mt=0; mt<2; mt++)
                #pragma unroll
                for (int nt=0; nt<4; nt++){
                    mma_bf16(acc[mt][nt], ah[mt], bh[nt]);
                    mma_bf16(acc[mt][nt], ah[mt], bl[nt]);
                    mma_bf16(acc[mt][nt], al[mt], bh[nt]);
                }
        }
        __syncthreads();
    }

    // ---- epilogue ----
    int gid = lane >> 2, tig = lane & 3;
    #pragma unroll
    for (int mt=0; mt<2; mt++){
        #pragma unroll
        for (int nt=0; nt<4; nt++){
            int col = n0 + wn*32 + nt*8 + tig*2;
            if (col >= 300) continue;
            float b0 = __ldg(&bias[col]);
            float b1 = __ldg(&bias[col+1]);
            int row0 = l0 + wm*32 + mt*16 + gid;
            int row1 = row0 + 8;
            if (row0 < Lout){
                float2 vv = make_float2(tanhf(acc[mt][nt][0] + b0),
                                        tanhf(acc[mt][nt][1] + b1));
                *(float2*)&out[((size_t)nb*Lout + row0)*300 + col] = vv;
            }
            if (row1 < Lout){
                float2 vv = make_float2(tanhf(acc[mt][nt][2] + b0),
                                        tanhf(acc[mt][nt][3] + b1));
                *(float2*)&out[((size_t)nb*Lout + row1)*300 + col] = vv;
            }
        }
    }
}

// ---------------- transpose [n][L][300] -> [n][300][L] ----------------
__global__ void __launch_bounds__(256) transpose300_kernel(
        const float* __restrict__ src, float* __restrict__ dst, int L){
    __shared__ float t[32][33];
    int n = blockIdx.z;
    int o0 = blockIdx.x*32, l0 = blockIdx.y*32;
    int x = threadIdx.x, y = threadIdx.y;   // (32, 8)
    #pragma unroll
    for (int i=0;i<4;i++){
        int l = l0 + y + i*8, o = o0 + x;
        if (l < L && o < 300) t[y+i*8][x] = src[((size_t)n*L + l)*300 + o];
    }
    __syncthreads();
    #pragma unroll
    for (int i=0;i<4;i++){
        int o = o0 + y + i*8, l = l0 + x;
        if (o < 300 && l < L) dst[((size_t)n*300 + o)*L + l] = t[x][y+i*8];
    }
}

// block-wide exclusive scan (warp shfl). sh: int[>=8].
__device__ __forceinline__ int block_scan_excl(int v, int tid, int* sh, int* total){
    int lane = tid & 31, w = tid >> 5;
    int x = v;
    #pragma unroll
    for (int off=1; off<32; off<<=1){
        int t = __shfl_up_sync(0xffffffffu, x, off);
        if (lane >= off) x += t;
    }
    if (lane == 31) sh[w] = x;
    __syncthreads();
    if (tid < 8){
        int t = sh[tid];
        #pragma unroll
        for (int off=1; off<8; off<<=1){
            int u = __shfl_up_sync(0xffu, t, off);
            if (tid >= off) t += u;
        }
        sh[tid] = t;
    }
    __syncthreads();
    int base = (w == 0) ? 0 : sh[w-1];
    *total = sh[7];
    int res = base + x - v;
    __syncthreads();
    return res;
}

// radix-select top-k, order preserved, ties by lowest index.
__device__ void topk_select(const unsigned* skey, int n, int k, short* out_idx,
                            int* hist, int* sws, int tid){
    unsigned prefix = 0;
    int kr = k;
    #pragma unroll
    for (int pass=0; pass<4; pass++){
        int shift = 24 - 8*pass;
        for (int i=tid; i<256; i+=BT) hist[i] = 0;
        __syncthreads();
        if (pass == 0){
            for (int i=tid; i<n; i+=BT) atomicAdd(&hist[skey[i] >> 24], 1);
        } else {
            int hs = shift + 8;
            for (int i=tid; i<n; i+=BT){
                unsigned v = skey[i];
                if ((v >> hs) == prefix) atomicAdd(&hist[(v >> shift) & 255u], 1);
            }
        }
        __syncthreads();
        if (tid < 32){
            int base = tid * 8;
            int h[8]; int tot = 0;
            #pragma unroll
            for (int j=0; j<8; j++){ h[j] = hist[base+j]; tot += h[j]; }
            int run = tot;
            #pragma unroll
            for (int off=1; off<32; off<<=1){
                int t = __shfl_down_sync(0xffffffffu, run, off);
                if (tid + off < 32) run += t;
            }
            int acc = run - tot;
            #pragma unroll
            for (int j=7; j>=0; j--){ acc += h[j]; sws[base+j] = acc; }
        }
        __syncthreads();
        int cum  = sws[tid];
        int cumn = (tid < 255) ? sws[tid+1] : 0;
        if (cum >= kr && cumn < kr){
            sws[256] = tid;
            hist[0]  = cumn;
        }
        __syncthreads();
        int d = sws[256];
        kr -= hist[0];
        prefix = (prefix << 8) | (unsigned)d;
        __syncthreads();
    }
    unsigned T = prefix;
    int m_eq = kr;

    int ipt = (n + BT - 1)/BT;
    int beg = tid*ipt; if (beg > n) beg = n;
    int end = beg + ipt; if (end > n) end = n;

    int ceq = 0;
    for (int i=beg; i<end; i++) ceq += (skey[i] == T);
    int tot;
    int eq_base = block_scan_excl(ceq, tid, sws, &tot);

    int csel = 0;
    { int eqr = eq_base;
      for (int i=beg; i<end; i++){
          unsigned v = skey[i]; int e = (v == T);
          csel += (v > T) || (e && eqr < m_eq);
          eqr += e;
      } }
    int out_base = block_scan_excl(csel, tid, sws, &tot);
    { int eqr = eq_base, p = out_base;
      for (int i=beg; i<end; i++){
          unsigned v = skey[i]; int e = (v == T);
          if ((v > T) || (e && eqr < m_eq)) out_idx[p++] = (short)i;
          eqr += e;
      } }
    __syncthreads();
}

// ---------------- pad kernels ----------------
__global__ void __launch_bounds__(256) pad_rows_kernel(
        float* dst, const float* __restrict__ src,
        int L, int C, int srcRowsPerItem, int srcRowOffset){
    int n = blockIdx.y;
    int idx = blockIdx.x*blockDim.x + threadIdx.x;
    int LP = L + 8;
    if (idx >= LP*C) return;
    int l = idx / C, c = idx - l*C;
    float v = 0.f;
    if (l >= 4 && l < 4+L)
        v = src[((size_t)n*srcRowsPerItem + srcRowOffset + (l-4))*C + c];
    dst[(size_t)n*LP*C + idx] = v;
}

__global__ void __launch_bounds__(256) pad_docs_kernel(
        float* dst, const float* __restrict__ pos, const float* __restrict__ neg){
    const int LP = 487, C = 1024, L = 479;
    int n = blockIdx.y;
    int idx = blockIdx.x*blockDim.x + threadIdx.x;
    if (idx >= LP*C) return;
    int l = idx / C, c = idx - l*C;
    float v = 0.f;
    if (l >= 4 && l < 4+L){
        int s = n >> 4, b = n & 15;
        const float* src = (s==0) ? (pos + (size_t)b*L*C)
                                  : (neg + ((size_t)(s-1)*16 + b)*L*C);
        v = src[(size_t)(l-4)*C + c];
    }
    dst[(size_t)n*LP*C + idx] = v;
}

// ---------------- kmax over channel axis (1024 -> 300) ----------------
__global__ void __launch_bounds__(256) kmax_last1024_kernel(
        const float* __restrict__ src, int Lpad,
        float* __restrict__ dst, int dstNstride){
    __shared__ unsigned skey[1024];
    __shared__ int      hist[256];
    __shared__ int      sws[257];
    __shared__ short    sidx[300];
    int tid = threadIdx.x;
    int l = blockIdx.x, n = blockIdx.y;
    const float* row = src + ((size_t)n*Lpad + 4 + l)*1024;
    for (int i=tid; i<1024; i+=BT) skey[i] = f2u(row[i]);
    __syncthreads();
    topk_select(skey, 1024, 300, sidx, hist, sws, tid);
    float* orow = dst + (size_t)n*dstNstride + (size_t)l*300;
    for (int j=tid; j<300; j+=BT) orow[j] = u2f(skey[sidx[j]]);
}

// ---------------- kmax over length axis, transposed input [n][300][Lin] -----
__global__ void __launch_bounds__(256) kmax_len_t_kernel(
        const float* __restrict__ srcT, int Lin, int k,
        float* __restrict__ dstBase, int dstNstride){
    __shared__ unsigned skey[512];
    __shared__ int      hist[256];
    __shared__ int      sws[257];
    __shared__ short    sidx[320];
    int tid = threadIdx.x;
    int o = blockIdx.x, n = blockIdx.y;
    const float* row = srcT + ((size_t)n*300 + o)*Lin;
    for (int l=tid; l<Lin; l+=BT) skey[l] = f2u(row[l]);
    __syncthreads();
    topk_select(skey, Lin, k, sidx, hist, sws, tid);
    float* dn = dstBase + (size_t)n*dstNstride;
    for (int j=tid; j<k; j+=BT)
        dn[(size_t)j*300 + o] = u2f(skey[sidx[j]]);
}

// ---------------- k=1: plain max over length (strided, small) ---------------
__global__ void __launch_bounds__(256) maxlen_kernel(
        const float* __restrict__ src, int Lin,
        float* __restrict__ dstBase, int dstNstride){
    int w = threadIdx.x >> 5, lane = threadIdx.x & 31;
    int o = blockIdx.x*8 + w;
    int n = blockIdx.y;
    if (o >= 300) return;
    float m = -FLT_MAX;
    for (int l=lane; l<Lin; l+=32)
        m = fmaxf(m, src[((size_t)n*Lin + l)*300 + o]);
    #pragma unroll
    for (int off=16; off; off>>=1)
        m = fmaxf(m, __shfl_down_sync(0xffffffffu, m, off));
    if (lane == 0) dstBase[(size_t)n*dstNstride + o] = m;
}

// ---------------- generic SGEMM (f32x2) ----------------
__global__ void __launch_bounds__(256) sgemm_kernel(
        const float* __restrict__ A, const float* __restrict__ B,
        float* __restrict__ C, int M, int N, int K){
    __shared__ float sA[16][68];
    __shared__ float sB[16][68];
    int tid = threadIdx.x;
    int tx = tid & 15, ty = tid >> 4;
    int n0 = blockIdx.x * 64, m0 = blockIdx.y * 64;
    unsigned long long acc2[4][2];
    #pragma unroll
    for (int i=0;i<4;i++){ acc2[i][0]=0ull; acc2[i][1]=0ull; }
    int row = ty*4, col = tx*4;
    for (int k0 = 0; k0 < K; k0 += 16){
        for (int idx = tid; idx < 1024; idx += BT){
            int kk = idx & 15, m = idx >> 4;
            int gm = m0 + m, gk = k0 + kk;
            sA[kk][m] = (gm < M && gk < K) ? A[(size_t)gm*K + gk] : 0.f;
        }
        for (int idx = tid; idx < 1024; idx += BT){
            int nn = idx & 63, kk = idx >> 6;
            int gn = n0 + nn, gk = k0 + kk;
            sB[kk][nn] = (gn < N && gk < K) ? B[(size_t)gk*N + gn] : 0.f;
        }
        __syncthreads();
        #pragma unroll
        for (int kk=0; kk<16; kk++){
            float4 a4 = *(const float4*)&sA[kk][row];
            ulonglong2 b2 = *(const ulonglong2*)&sB[kk][col];
            unsigned long long d0 = pk2(a4.x,a4.x);
            unsigned long long d1 = pk2(a4.y,a4.y);
            unsigned long long d2 = pk2(a4.z,a4.z);
            unsigned long long d3 = pk2(a4.w,a4.w);
            fma2(acc2[0][0], d0, b2.x); fma2(acc2[0][1], d0, b2.y);
            fma2(acc2[1][0], d1, b2.x); fma2(acc2[1][1], d1, b2.y);
            fma2(acc2[2][0], d2, b2.x); fma2(acc2[2][1], d2, b2.y);
            fma2(acc2[3][0], d3, b2.x); fma2(acc2[3][1], d3, b2.y);
        }
        __syncthreads();
    }
    #pragma unroll
    for (int i=0;i<4;i++){
        int gm = m0 + row + i;
        if (gm >= M) continue;
        #pragma unroll
        for (int j2=0;j2<2;j2++){
            float2 v = upk2(acc2[i][j2]);
            int gn = n0 + col + 2*j2;
            if (gn < N)   C[(size_t)gm*N + gn]   = v.x;
            if (gn+1 < N) C[(size_t)gm*N + gn+1] = v.y;
        }
    }
}

// ---------------- fused match GEMM + 12x24 max-pool + sigmoid (f32x2) -------
__global__ void __launch_bounds__(288) mpool_kernel(
        const float* __restrict__ qt, const float* __restrict__ dg,
        const float* __restrict__ bbp, float* __restrict__ xout){
    __shared__ float sQ[20][52];
    __shared__ float sD[20][100];
    __shared__ unsigned pool[16];
    int tid = threadIdx.x;
    int n = blockIdx.z, b = n & 15;
    int q0 = blockIdx.y * 48, d0 = blockIdx.x * 96;
    int tq = tid % 12, td = tid / 12;
    const float* Q = qt + (size_t)b * 480 * 300;
    const float* D = dg + (size_t)n * 960 * 300;
    unsigned long long acc2[4][2];
    #pragma unroll
    for (int i=0;i<4;i++){ acc2[i][0]=0ull; acc2[i][1]=0ull; }
    for (int c0 = 0; c0 < 300; c0 += 20){
        for (int idx = tid; idx < 48*20; idx += 288){
            int kk = idx % 20, r = idx / 20;
            sQ[kk][r] = Q[(size_t)(q0 + r)*300 + c0 + kk];
        }
        for (int idx = tid; idx < 96*20; idx += 288){
            int kk = idx % 20, r = idx / 20;
            sD[kk][r] = D[(size_t)(d0 + r)*300 + c0 + kk];
        }
        __syncthreads();
        #pragma unroll
        for (int kk=0; kk<20; kk++){
            float4 aq = *(const float4*)&sQ[kk][tq*4];
            ulonglong2 b2 = *(const ulonglong2*)&sD[kk][td*4];
            unsigned long long d0r = pk2(aq.x,aq.x);
            unsigned long long d1r = pk2(aq.y,aq.y);
            unsigned long long d2r = pk2(aq.z,aq.z);
            unsigned long long d3r = pk2(aq.w,aq.w);
            fma2(acc2[0][0], d0r, b2.x); fma2(acc2[0][1], d0r, b2.y);
            fma2(acc2[1][0], d1r, b2.x); fma2(acc2[1][1], d1r, b2.y);
            fma2(acc2[2][0], d2r, b2.x); fma2(acc2[2][1], d2r, b2.y);
            fma2(acc2[3][0], d3r, b2.x); fma2(acc2[3][1], d3r, b2.y);
        }
        __syncthreads();
    }
    float m = -FLT_MAX;
    #pragma unroll
    for (int i=0;i<4;i++)
        #pragma unroll
        for (int j2=0;j2<2;j2++){
            float2 v = upk2(acc2[i][j2]);
            m = fmaxf(m, fmaxf(v.x, v.y));
        }
    if (tid < 16) pool[tid] = 0u;
    __syncthreads();
    int ci = tq/3, cj = td/6;
    atomicMax(&pool[ci*4 + cj], f2u(m));
    __syncthreads();
    if (tid < 16){
        int pi = tid >> 2, pj = tid & 3;
        float logit = u2f(pool[tid]) + bbp[0];
        int gi = blockIdx.y*4 + pi, gj = blockIdx.x*4 + pj;
        xout[((size_t)n*40 + gi)*40 + gj] = sigm(logit);
    }
}

// ---------------- 2D conv tower block ----------------
__global__ void __launch_bounds__(256) convtower_kernel(
        const float* __restrict__ xin, const float* __restrict__ mw,
        const float* __restrict__ mb, float* __restrict__ xout){
    __shared__ float sx[40][40];
    __shared__ float swt[50][4];
    __shared__ float sb[50];
    int n = blockIdx.x, tid = threadIdx.x;
    for (int idx=tid; idx<1600; idx+=blockDim.x)
        sx[idx/40][idx%40] = xin[(size_t)n*1600 + idx];
    for (int idx=tid; idx<200; idx+=blockDim.x)
        swt[idx>>2][idx&3] = mw[idx];
    for (int idx=tid; idx<50; idx+=blockDim.x)
        sb[idx] = mb[idx];
    __syncthreads();
    for (int cell=tid; cell<1600; cell+=blockDim.x){
        int i = cell/40, j = cell%40;
        int hs = (i*47)/40,  he = ((i+1)*47 + 39)/40;
        int ws = (j*47)/40,  we = ((j+1)*47 + 39)/40;
        float m = -FLT_MAX;
        for (int h=hs; h<he; h++)
            for (int w=ws; w<we; w++){
                int r0=h-4, r1=h-3, c0=w-4, c1=w-3;
                float x00 = (r0>=0 && r0<40 && c0>=0 && c0<40) ? sx[r0][c0] : 0.f;
                float x01 = (r0>=0 && r0<40 && c1>=0 && c1<40) ? sx[r0][c1] : 0.f;
                float x10 = (r1>=0 && r1<40 && c0>=0 && c0<40) ? sx[r1][c0] : 0.f;
                float x11 = (r1>=0 && r1<40 && c1>=0 && c1<40) ? sx[r1][c1] : 0.f;
                for (int o=0;o<50;o++){
                    float l = fmaf(x00, swt[o][0],
                              fmaf(x01, swt[o][1],
                              fmaf(x10, swt[o][2],
                              fmaf(x11, swt[o][3], sb[o]))));
                    m = fmaxf(m, l);
                }
            }
        xout[(size_t)n*1600 + cell] = sigm(m);
    }
}

// ---------------- final logistic head ----------------
__global__ void __launch_bounds__(64) final_kernel(
        const float* __restrict__ feat, const float* __restrict__ lw,
        const float* __restrict__ lb, float* __restrict__ out){
    __shared__ float sh[40];
    int n = blockIdx.x, tid = threadIdx.x;
    if (tid < 40){
        float a = 0.f;
        const float* f = feat + (size_t)n*1600 + tid*40;
        for (int j=0;j<40;j++) a += f[j]*lw[j];
        sh[tid] = sigm(a + lb[0]);
    }
    __syncthreads();
    if (tid == 0){
        float a = 0.f;
        for (int i=0;i<40;i++) a += sh[i]*lw[i];
        out[n] = sigm(a + lb[0]);
    }
}

// ---------------- launch ----------------
extern "C" void kernel_launch(void* const* d_in, const int* in_sizes, int n_in,
                              void* d_out, int out_size){
    const float* query = (const float*)d_in[0];
    const float* pos   = (const float*)d_in[1];
    const float* neg   = (const float*)d_in[2];
    const float* qw1 = (const float*)d_in[3];  const float* qb1 = (const float*)d_in[4];
    const float* qw2 = (const float*)d_in[5];  const float* qb2 = (const float*)d_in[6];
    const float* qw3 = (const float*)d_in[7];  const float* qb3 = (const float*)d_in[8];
    const float* dw1 = (const float*)d_in[9];  const float* db1 = (const float*)d_in[10];
    const float* dw2 = (const float*)d_in[11]; const float* db2 = (const float*)d_in[12];
    const float* dw3 = (const float*)d_in[13]; const float* db3 = (const float*)d_in[14];
    const float* bw  = (const float*)d_in[15]; const float* bb  = (const float*)d_in[16];
    const float* mw1 = (const float*)d_in[17]; const float* mb1 = (const float*)d_in[18];
    const float* mw2 = (const float*)d_in[19]; const float* mb2 = (const float*)d_in[20];
    const float* mw3 = (const float*)d_in[21]; const float* mb3 = (const float*)d_in[22];
    const float* lw  = (const float*)d_in[23]; const float* lb  = (const float*)d_in[24];
    float* out = (float*)d_out;

    float *qpad, *qc1, *qp1p, *qc2, *qp2p, *qc3, *qg;
    float *dpad, *dc1, *dp1p, *dc2, *dp2p, *dc3, *dg;
    float *qt, *x0, *x1;
    cudaGetSymbolAddress((void**)&qpad, g_qpad);
    cudaGetSymbolAddress((void**)&qc1,  g_qc1);
    cudaGetSymbolAddress((void**)&qp1p, g_qp1p);
    cudaGetSymbolAddress((void**)&qc2,  g_qc2);
    cudaGetSymbolAddress((void**)&qp2p, g_qp2p);
    cudaGetSymbolAddress((void**)&qc3,  g_qc3);
    cudaGetSymbolAddress((void**)&qg,   g_qg);
    cudaGetSymbolAddress((void**)&dpad, g_dpad);
    cudaGetSymbolAddress((void**)&dc1,  g_dc1);
    cudaGetSymbolAddress((void**)&dp1p, g_dp1p);
    cudaGetSymbolAddress((void**)&dc2,  g_dc2);
    cudaGetSymbolAddress((void**)&dp2p, g_dp2p);
    cudaGetSymbolAddress((void**)&dc3,  g_dc3);
    cudaGetSymbolAddress((void**)&dg,   g_dg);
    cudaGetSymbolAddress((void**)&qt,   g_qt);
    cudaGetSymbolAddress((void**)&x0,   g_x0);
    cudaGetSymbolAddress((void**)&x1,   g_x1);

    cudaFuncSetAttribute(conv1d_mma_kernel,
                         cudaFuncAttributeMaxDynamicSharedMemorySize, CONV_SMEM_SZ);

    const int QNS = 480*300;
    const int DNS = 960*300;

    pad_rows_kernel<<<dim3((247*1024 + 255)/256, 16), 256>>>(qpad, query, 239, 1024, 239, 0);
    pad_docs_kernel<<<dim3((487*1024 + 255)/256, 80), 256>>>(dpad, pos, neg);

    kmax_last1024_kernel<<<dim3(239, 16), 256>>>(qpad, 247, qg, QNS);
    kmax_last1024_kernel<<<dim3(479, 80), 256>>>(dpad, 487, dg, DNS);

    // ===== query tower =====
    conv1d_mma_kernel<<<dim3(2,5,16), 256, CONV_SMEM_SZ>>>(qpad, qw1, qb1, qc1, 247, 246, 1024);
    // qpad now dead -> reuse as transpose scratch
    transpose300_kernel<<<dim3(10, 8, 16), dim3(32,8)>>>(qc1, qpad, 246);
    kmax_len_t_kernel<<<dim3(300,16), 256>>>(qpad, 246, 160, qg + 239*300, QNS);
    pad_rows_kernel<<<dim3((168*300 + 255)/256, 16), 256>>>(qp1p, qg, 160, 300, 480, 239);
    conv1d_mma_kernel<<<dim3(2,5,16), 256, CONV_SMEM_SZ>>>(qp1p, qw2, qb2, qc2, 168, 167, 300);
    transpose300_kernel<<<dim3(10, 6, 16), dim3(32,8)>>>(qc2, qpad, 167);
    kmax_len_t_kernel<<<dim3(300,16), 256>>>(qpad, 167, 80, qg + 399*300, QNS);
    pad_rows_kernel<<<dim3((88*300 + 255)/256, 16), 256>>>(qp2p, qg, 80, 300, 480, 399);
    conv1d_mma_kernel<<<dim3(1,5,16), 256, CONV_SMEM_SZ>>>(qp2p, qw3, qb3, qc3, 88, 87, 300);
    maxlen_kernel<<<dim3(38,16), 256>>>(qc3, 87, qg + 479*300, QNS);

    // ===== doc tower =====
    conv1d_mma_kernel<<<dim3(4,5,80), 256, CONV_SMEM_SZ>>>(dpad, dw1, db1, dc1, 487, 486, 1024);
    // dpad now dead -> transpose scratch
    transpose300_kernel<<<dim3(10, 16, 80), dim3(32,8)>>>(dc1, dpad, 486);
    kmax_len_t_kernel<<<dim3(300,80), 256>>>(dpad, 486, 320, dg + 479*300, DNS);
    pad_rows_kernel<<<dim3((328*300 + 255)/256, 80), 256>>>(dp1p, dg, 320, 300, 960, 479);
    conv1d_mma_kernel<<<dim3(3,5,80), 256, CONV_SMEM_SZ>>>(dp1p, dw2, db2, dc2, 328, 327, 300);
    transpose300_kernel<<<dim3(10, 11, 80), dim3(32,8)>>>(dc2, dpad, 327);
    kmax_len_t_kernel<<<dim3(300,80), 256>>>(dpad, 327, 160, dg + 799*300, DNS);
    pad_rows_kernel<<<dim3((168*300 + 255)/256, 80), 256>>>(dp2p, dg, 160, 300, 960, 799);
    conv1d_mma_kernel<<<dim3(2,5,80), 256, CONV_SMEM_SZ>>>(dp2p, dw3, db3, dc3, 168, 167, 300);
    maxlen_kernel<<<dim3(38,80), 256>>>(dc3, 167, dg + 959*300, DNS);

    sgemm_kernel<<<dim3(5, 120), 256>>>(qg, bw, qt, 16*480, 300, 300);

    mpool_kernel<<<dim3(10, 10, 80), 288>>>(qt, dg, bb, x0);

    convtower_kernel<<<80, 256>>>(x0, mw1, mb1, x1);
    convtower_kernel<<<80, 256>>>(x1, mw2, mb2, x0);
    convtower_kernel<<<80, 256>>>(x0, mw3, mb3, x1);

    final_kernel<<<80, 64>>>(x1, lw, lb, out);
}